// round 7
// baseline (speedup 1.0000x reference)
#include <cuda_runtime.h>
#include <math.h>
#include <stdint.h>

// ============================================================================
// DyGNN streaming scan -> wave-parallel batched GEMMs (f32x2 packed FFMA).
// R5: 16-row tiles + atomic ticket queues per (wave,phase) to kill the
// block-quantization imbalance; init gather merged into the main kernel.
// ============================================================================

#define MAXS   2048
#define HSIZE  8192
#define HMASK  8191
#define NBLK   296
#define NTHR   256

#define EPI_NONE 0
#define EPI_TANH 1
#define EPI_CADJ 2

typedef unsigned long long ull;

struct Params {
  const int   *heads, *tails;
  const float *times;
  const float *node_rep, *cell_head, *hidden_head, *cell_tail, *hidden_tail;
  const float *Weh1, *Weh2, *beh, *Wet1, *Wet2, *bet;
  const float *Wxh, *Whh, *bh, *Wdh, *bdh;
  const float *Wxt, *Wht, *bt, *Wdt, *bdt;
  const float *Wc1, *Wc2;
  float *out;
  int S;
};

// ---------------- scheduler outputs ----------------
__device__ int g_cidH[MAXS], g_cidT[MAXS];
__device__ int g_slotNode[HSIZE];
__device__ int g_stepList[MAXS];
__device__ int g_waveOff[MAXS + 2];
__device__ int g_numWaves;
__device__ int g_tick[4096];

// ---------------- compact state tables (indexed by hash slot) --------------
__device__ float c_rep[HSIZE * 128];
__device__ float c_ch [HSIZE * 128];
__device__ float c_hh [HSIZE * 128];
__device__ float c_ct [HSIZE * 128];
__device__ float c_ht [HSIZE * 128];
__device__ float c_rt [HSIZE];

// ---------------- per-wave batch buffers (wave-local row index) -------------
__device__ float bEdgeH[MAXS * 128], bEdgeT[MAXS * 128];
__device__ float bCadjH[MAXS * 128], bCadjT[MAXS * 128];
__device__ float bHTh  [MAXS * 128], bHHt  [MAXS * 128];
__device__ float bHnH  [MAXS * 128], bHnT  [MAXS * 128];
__device__ float bZH   [MAXS * 512], bZT   [MAXS * 512];

// ---------------- grid barrier ----------------
__device__ unsigned g_barCnt;            // zero-init
__device__ volatile unsigned g_barGen;   // zero-init

__device__ __forceinline__ void grid_barrier() {
  __syncthreads();
  if (threadIdx.x == 0) {
    unsigned gen = g_barGen;
    __threadfence();
    if (atomicAdd(&g_barCnt, 1u) == gridDim.x - 1) {
      g_barCnt = 0;
      __threadfence();
      g_barGen = gen + 1;
    } else {
      while (g_barGen == gen) { __nanosleep(32); }
    }
    __threadfence();
  }
  __syncthreads();
}

__device__ __forceinline__ float sigf(float x) { return 1.0f / (1.0f + expf(-x)); }

__device__ __forceinline__ void FFMA2(ull &d, ull a, ull b) {
  asm("fma.rn.f32x2 %0, %1, %2, %0;" : "+l"(d) : "l"(a), "l"(b));
}

// ============================================================================
// Scheduler: hash compaction + peeling into waves. One block, 1024 threads.
// ============================================================================
__global__ void __launch_bounds__(1024) scheduler_kernel(const int* heads, const int* tails, int S) {
  __shared__ int buf[HSIZE];
  __shared__ unsigned short sCH[MAXS], sCT[MAXS];
  __shared__ unsigned char asg[MAXS];
  __shared__ int sCnt, sBase, sW, sRemain;

  const int tid = threadIdx.x;

  for (int i = tid; i < HSIZE; i += 1024) { buf[i] = 0; g_slotNode[i] = -1; }
  for (int s = tid; s < S; s += 1024) asg[s] = 0;
  for (int i = tid; i < 4096; i += 1024) g_tick[i] = 0;
  if (tid == 0) { sBase = 0; sW = 0; sRemain = S; }
  __syncthreads();

  // ---- insertion: slot = compact id ----
  for (int i = tid; i < 2 * S; i += 1024) {
    int step = i >> 1, isT = i & 1;
    int node = isT ? tails[step] : heads[step];
    int key = node + 1;
    unsigned slot = ((unsigned)node * 2654435761u) & HMASK;
    while (true) {
      int cur = buf[slot];
      if (cur == key) break;
      if (cur == 0) {
        int old = atomicCAS(&buf[slot], 0, key);
        if (old == 0) { g_slotNode[slot] = node; break; }
        if (old == key) break;
      }
      slot = (slot + 1u) & HMASK;
    }
    if (isT) { sCT[step] = (unsigned short)slot; g_cidT[step] = (int)slot; }
    else     { sCH[step] = (unsigned short)slot; g_cidH[step] = (int)slot; }
  }
  __syncthreads();

  // ---- peeling into waves ----
  while (sRemain > 0) {
    for (int s = tid; s < S; s += 1024)
      if (!asg[s]) { buf[sCH[s]] = 0x7FFFFFFF; buf[sCT[s]] = 0x7FFFFFFF; }
    __syncthreads();
    for (int s = tid; s < S; s += 1024)
      if (!asg[s]) {
        atomicMin(&buf[sCH[s]], 2 * s);
        atomicMin(&buf[sCT[s]], 2 * s + 1);
      }
    if (tid == 0) sCnt = 0;
    __syncthreads();
    for (int s = tid; s < S; s += 1024)
      if (!asg[s]) {
        int ch = sCH[s], ct = sCT[s];
        if (buf[ch] == 2 * s && (ct == ch || buf[ct] == 2 * s + 1)) {
          asg[s] = 1;
          int pos = atomicAdd(&sCnt, 1);
          g_stepList[sBase + pos] = s;
        }
      }
    __syncthreads();
    if (tid == 0) {
      g_waveOff[sW] = sBase;
      sBase += sCnt;
      sRemain -= sCnt;
      sW += 1;
      g_waveOff[sW] = sBase;
    }
    __syncthreads();
  }
  if (tid == 0) g_numWaves = sW;
}

// ============================================================================
// 16x128 GEMM tile, f32x2 packed FFMA, 2x4 micro-tile per thread (256 thr).
// Y[tile] = epi( A1@W1 (+ A2@W2) + bias ), K=128 per operand pair.
// A rows / outputs via per-row pointers (fused gather/scatter; null => skip).
// ============================================================================
__device__ void gemm16(const float* __restrict__ W1, const float* __restrict__ W2,
                       bool dual, int ldw, int n0,
                       const float* __restrict__ bias, int epi,
                       const float* const* sA1, const float* const* sA2,
                       float* const* sOut, const float* sDec,
                       float (*AsT2)[32], float (*Ws)[128]) {
  const int tid = threadIdx.x;
  const int wid = tid >> 5;
  const int lane = tid & 31;

  ull acc00 = 0, acc01 = 0, acc10 = 0, acc11 = 0;

  const int npair = dual ? 2 : 1;
  for (int pair = 0; pair < npair; ++pair) {
    for (int k0 = 0; k0 < 128; k0 += 32) {
      if (tid < 128) {
        int r = tid & 15;
        int kq = (tid >> 4) << 2;
        const float* src = pair ? sA2[r] : sA1[r];
        float4 av = *(const float4*)(src + k0 + kq);
        *(float2*)&AsT2[kq + 0][2 * r] = make_float2(av.x, av.x);
        *(float2*)&AsT2[kq + 1][2 * r] = make_float2(av.y, av.y);
        *(float2*)&AsT2[kq + 2][2 * r] = make_float2(av.z, av.z);
        *(float2*)&AsT2[kq + 3][2 * r] = make_float2(av.w, av.w);
      }
#pragma unroll
      for (int j = 0; j < 4; ++j) {
        int lin = tid + j * NTHR;
        int kk = lin >> 5, c4 = (lin & 31) << 2;
        *(float4*)&Ws[kk][c4] = *(const float4*)(W1 == 0 ? 0 :
            ((pair ? W2 : W1) + (size_t)(k0 + kk) * ldw + n0 + c4));
      }
      __syncthreads();
#pragma unroll
      for (int kk = 0; kk < 32; ++kk) {
        ull a0 = *(const ull*)&AsT2[kk][4 * wid];
        ull a1 = *(const ull*)&AsT2[kk][4 * wid + 2];
        ulonglong2 wv = *(const ulonglong2*)&Ws[kk][lane << 2];
        FFMA2(acc00, a0, wv.x); FFMA2(acc01, a0, wv.y);
        FFMA2(acc10, a1, wv.x); FFMA2(acc11, a1, wv.y);
      }
      __syncthreads();
    }
  }

  union U { ull u; float2 f; };
#pragma unroll
  for (int i = 0; i < 2; i++) {
    int r = 2 * wid + i;
    float* o = sOut[r];
    if (!o) continue;
    U u0, u1;
    u0.u = i ? acc10 : acc00;
    u1.u = i ? acc11 : acc01;
    float vals[4] = {u0.f.x, u0.f.y, u1.f.x, u1.f.y};
#pragma unroll
    for (int j = 0; j < 4; j++) {
      int cin = (lane << 2) + j;
      float v = vals[j];
      if (bias) v += bias[cin];
      if (epi == EPI_TANH) {
        v = tanhf(v);
      } else if (epi == EPI_CADJ) {
        float cs = tanhf(v);
        float cp = sA1[r][cin];
        v = cp + cs * (sDec[r] - 1.0f);
      }
      o[cin] = v;
    }
  }
}

// ============================================================================
// Persistent cooperative main kernel (init gather + waves). 2 blocks/SM.
// ============================================================================
__global__ void __launch_bounds__(NTHR, 2) main_kernel(Params p) {
  __shared__ float AsT2[32][32];
  __shared__ float Ws[32][128];
  __shared__ const float* sA1[16];
  __shared__ const float* sA2[16];
  __shared__ float* sOut[16];
  __shared__ float sDec[16];
  __shared__ int sJob;

  const int tid = threadIdx.x;
  const int gsize = gridDim.x * blockDim.x;
  const int gtid = blockIdx.x * blockDim.x + tid;
  const int S = p.S;

  // -------- init gather of touched rows into compact tables ---------------
  for (int e = gtid; e < HSIZE * 32; e += gsize) {
    int slot = e >> 5, q = (e & 31) << 2;
    int node = g_slotNode[slot];
    if (node < 0) continue;
    size_t src = (size_t)node * 128 + q;
    size_t dst = (size_t)slot * 128 + q;
    *(float4*)&c_rep[dst] = *(const float4*)&p.node_rep[src];
    *(float4*)&c_ch[dst]  = *(const float4*)&p.cell_head[src];
    *(float4*)&c_hh[dst]  = *(const float4*)&p.hidden_head[src];
    *(float4*)&c_ct[dst]  = *(const float4*)&p.cell_tail[src];
    *(float4*)&c_ht[dst]  = *(const float4*)&p.hidden_tail[src];
    if (q == 0) c_rt[slot] = 0.0f;
  }
  grid_barrier();

  const int nW = g_numWaves;

  for (int w = 0; w < nW; ++w) {
    const int s0 = g_waveOff[w];
    const int M = g_waveOff[w + 1] - s0;
    const int mT = (M + 15) >> 4;
    int* tick = &g_tick[(w * 3) & 4095];

    // -------- Phase B: edge GEMMs, cadj GEMMs, copies --------
    {
      const int nJobs = mT * 5;
      for (;;) {
        __syncthreads();
        if (tid == 0) sJob = atomicAdd(&tick[0], 1);
        __syncthreads();
        int j = sJob;
        if (j >= nJobs) break;
        if (j >= 4 * mT) {
          // copy job: out emission + pre-update hidden stash
          int m0 = (j - 4 * mT) * 16;
          for (int l = tid; l < 16 * 32; l += NTHR) {
            int r = l >> 5, q = (l & 31) << 2;
            int m = m0 + r;
            if (m >= M) continue;
            int step = g_stepList[s0 + m];
            int ch = g_cidH[step], ct = g_cidT[step];
            float4 rh = *(const float4*)&c_rep[ch * 128 + q];
            float4 rt = *(const float4*)&c_rep[ct * 128 + q];
            *(float4*)&p.out[(size_t)step * 128 + q] = rh;
            *(float4*)&p.out[(size_t)(S + step) * 128 + q] = rt;
            *(float4*)&bHTh[m * 128 + q] = *(const float4*)&c_ht[ch * 128 + q];
            *(float4*)&bHHt[m * 128 + q] = *(const float4*)&c_hh[ct * 128 + q];
          }
          continue;
        }
        int kind, m0;
        if (j < 2 * mT) { kind = j & 1; m0 = (j >> 1) * 16; }            // edge
        else { int jj = j - 2 * mT; kind = 2 + (jj & 1); m0 = (jj >> 1) * 16; }  // cadj
        if (tid < 16) {
          int m = m0 + tid;
          bool v = m < M;
          int step = g_stepList[s0 + (v ? m : 0)];
          int ch = g_cidH[step], ct = g_cidT[step];
          const float *a1, *a2 = 0; float* o = 0; float dc = 1.0f;
          if (kind == 0)      { a1 = c_rep + ch * 128; a2 = c_rep + ct * 128; o = bEdgeH + m * 128; }
          else if (kind == 1) { a1 = c_rep + ch * 128; a2 = c_rep + ct * 128; o = bEdgeT + m * 128; }
          else if (kind == 2) { a1 = c_ch + ch * 128; o = bCadjH + m * 128;
                                dc = expf(-(p.times[step] - c_rt[ch])); }
          else                { a1 = c_ct + ct * 128; o = bCadjT + m * 128;
                                dc = expf(-(p.times[step] - c_rt[ct])); }
          sA1[tid] = a1; sA2[tid] = a2; sOut[tid] = v ? o : 0; sDec[tid] = dc;
        }
        __syncthreads();
        if (kind == 0)
          gemm16(p.Weh1, p.Weh2, true, 128, 0, p.beh, EPI_TANH, sA1, sA2, sOut, sDec, AsT2, Ws);
        else if (kind == 1)
          gemm16(p.Wet1, p.Wet2, true, 128, 0, p.bet, EPI_TANH, sA1, sA2, sOut, sDec, AsT2, Ws);
        else if (kind == 2)
          gemm16(p.Wdh, 0, false, 128, 0, p.bdh, EPI_CADJ, sA1, sA2, sOut, sDec, AsT2, Ws);
        else
          gemm16(p.Wdt, 0, false, 128, 0, p.bdt, EPI_CADJ, sA1, sA2, sOut, sDec, AsT2, Ws);
      }
    }
    grid_barrier();

    // -------- Phase C: LSTM gate GEMMs (z = edge@Wx + h@Wh + b), N=512 -----
    {
      const int nJobs = mT * 8;
      for (;;) {
        __syncthreads();
        if (tid == 0) sJob = atomicAdd(&tick[1], 1);
        __syncthreads();
        int j = sJob;
        if (j >= nJobs) break;
        int side = j & 1, nt = (j >> 1) & 3, mt = j >> 3;
        int m0 = mt * 16, n0 = nt * 128;
        if (tid < 16) {
          int m = m0 + tid;
          bool v = m < M;
          int step = g_stepList[s0 + (v ? m : 0)];
          if (side == 0) {
            int ch = g_cidH[step];
            sA1[tid] = bEdgeH + m * 128;
            sA2[tid] = c_hh + ch * 128;
            sOut[tid] = v ? (bZH + m * 512 + n0) : 0;
          } else {
            int ct = g_cidT[step];
            sA1[tid] = bEdgeT + m * 128;
            sA2[tid] = c_ht + ct * 128;
            sOut[tid] = v ? (bZT + m * 512 + n0) : 0;
          }
        }
        __syncthreads();
        if (side == 0)
          gemm16(p.Wxh, p.Whh, true, 512, n0, p.bh + n0, EPI_NONE, sA1, sA2, sOut, sDec, AsT2, Ws);
        else
          gemm16(p.Wxt, p.Wht, true, 512, n0, p.bt + n0, EPI_NONE, sA1, sA2, sOut, sDec, AsT2, Ws);
      }
    }
    grid_barrier();

    // -------- Phase D: gates elementwise + cell/hidden/rt scatter ---------
    for (int e = gtid; e < M * 128; e += gsize) {
      int s = e >> 7, d = e & 127;
      int step = g_stepList[s0 + s];
      int ch = g_cidH[step], ct = g_cidT[step];
      {
        float zi = bZH[s * 512 + d];
        float zf = bZH[s * 512 + 128 + d];
        float zo = bZH[s * 512 + 256 + d];
        float zg = bZH[s * 512 + 384 + d];
        float ii = sigf(zi), ff = sigf(zf), oo = sigf(zo), gg = tanhf(zg);
        float cn = ff * bCadjH[s * 128 + d] + ii * gg;
        float hn = oo * tanhf(cn);
        bHnH[s * 128 + d] = hn;
        c_ch[ch * 128 + d] = cn;
        c_hh[ch * 128 + d] = hn;
      }
      {
        float zi = bZT[s * 512 + d];
        float zf = bZT[s * 512 + 128 + d];
        float zo = bZT[s * 512 + 256 + d];
        float zg = bZT[s * 512 + 384 + d];
        float ii = sigf(zi), ff = sigf(zf), oo = sigf(zo), gg = tanhf(zg);
        float cn = ff * bCadjT[s * 128 + d] + ii * gg;
        float hn = oo * tanhf(cn);
        bHnT[s * 128 + d] = hn;
        c_ct[ct * 128 + d] = cn;
        c_ht[ct * 128 + d] = hn;
      }
      if (d == 0) {
        float tm = p.times[step];
        c_rt[ch] = tm;
        c_rt[ct] = tm;
      }
    }
    grid_barrier();

    // -------- Phase E: combiner GEMMs with fused rep scatter ---------------
    {
      const int nJobs = mT * 2;
      for (;;) {
        __syncthreads();
        if (tid == 0) sJob = atomicAdd(&tick[2], 1);
        __syncthreads();
        int j = sJob;
        if (j >= nJobs) break;
        int side = j & 1, mt = j >> 1;
        int m0 = mt * 16;
        if (tid < 16) {
          int m = m0 + tid;
          bool v = m < M;
          int step = g_stepList[s0 + (v ? m : 0)];
          int ch = g_cidH[step], ct = g_cidT[step];
          if (side == 0) {
            sA1[tid] = bHnH + m * 128;
            sA2[tid] = bHTh + m * 128;
            sOut[tid] = (v && ch != ct) ? (c_rep + ch * 128) : 0;  // tail wins on h==t
          } else {
            sA1[tid] = bHHt + m * 128;
            sA2[tid] = bHnT + m * 128;
            sOut[tid] = v ? (c_rep + ct * 128) : 0;
          }
        }
        __syncthreads();
        gemm16(p.Wc1, p.Wc2, true, 128, 0, 0, EPI_TANH, sA1, sA2, sOut, sDec, AsT2, Ws);
      }
    }
    grid_barrier();
  }
}

// ============================================================================
extern "C" void kernel_launch(void* const* d_in, const int* in_sizes, int n_in,
                              void* d_out, int out_size) {
  Params p;
  p.heads       = (const int*)d_in[0];
  p.tails       = (const int*)d_in[1];
  p.times       = (const float*)d_in[2];
  p.node_rep    = (const float*)d_in[3];
  p.cell_head   = (const float*)d_in[4];
  p.hidden_head = (const float*)d_in[5];
  p.cell_tail   = (const float*)d_in[6];
  p.hidden_tail = (const float*)d_in[7];
  p.Weh1 = (const float*)d_in[8];
  p.Weh2 = (const float*)d_in[9];
  p.beh  = (const float*)d_in[10];
  p.Wet1 = (const float*)d_in[11];
  p.Wet2 = (const float*)d_in[12];
  p.bet  = (const float*)d_in[13];
  p.Wxh  = (const float*)d_in[14];
  p.Whh  = (const float*)d_in[15];
  p.bh   = (const float*)d_in[16];
  p.Wdh  = (const float*)d_in[17];
  p.bdh  = (const float*)d_in[18];
  p.Wxt  = (const float*)d_in[19];
  p.Wht  = (const float*)d_in[20];
  p.bt   = (const float*)d_in[21];
  p.Wdt  = (const float*)d_in[22];
  p.bdt  = (const float*)d_in[23];
  p.Wc1  = (const float*)d_in[24];
  p.Wc2  = (const float*)d_in[25];
  p.out  = (float*)d_out;
  p.S    = in_sizes[0];

  scheduler_kernel<<<1, 1024>>>(p.heads, p.tails, p.S);
  main_kernel<<<NBLK, NTHR>>>(p);
}

// round 8
// speedup vs baseline: 1.5987x; 1.5987x over previous
#include <cuda_runtime.h>
#include <math.h>
#include <stdint.h>

// ============================================================================
// DyGNN streaming scan -> wave-parallel batched GEMMs (f32x2 packed FFMA).
// R5: 16-row tiles + atomic ticket queues per (wave,phase) to kill the
// block-quantization imbalance; init gather merged into the main kernel.
// ============================================================================

#define MAXS   2048
#define HSIZE  8192
#define HMASK  8191
#define NBLK   296
#define NTHR   256

#define EPI_NONE 0
#define EPI_TANH 1
#define EPI_CADJ 2

typedef unsigned long long ull;

struct Params {
  const int   *heads, *tails;
  const float *times;
  const float *node_rep, *cell_head, *hidden_head, *cell_tail, *hidden_tail;
  const float *Weh1, *Weh2, *beh, *Wet1, *Wet2, *bet;
  const float *Wxh, *Whh, *bh, *Wdh, *bdh;
  const float *Wxt, *Wht, *bt, *Wdt, *bdt;
  const float *Wc1, *Wc2;
  float *out;
  int S;
};

// ---------------- scheduler outputs ----------------
__device__ int g_cidH[MAXS], g_cidT[MAXS];
__device__ int g_slotNode[HSIZE];
__device__ int g_stepList[MAXS];
__device__ int g_waveOff[MAXS + 2];
__device__ int g_numWaves;
__device__ int g_tick[4096];

// ---------------- compact state tables (indexed by hash slot) --------------
__device__ float c_rep[HSIZE * 128];
__device__ float c_ch [HSIZE * 128];
__device__ float c_hh [HSIZE * 128];
__device__ float c_ct [HSIZE * 128];
__device__ float c_ht [HSIZE * 128];
__device__ float c_rt [HSIZE];

// ---------------- per-wave batch buffers (wave-local row index) -------------
__device__ float bEdgeH[MAXS * 128], bEdgeT[MAXS * 128];
__device__ float bCadjH[MAXS * 128], bCadjT[MAXS * 128];
__device__ float bHTh  [MAXS * 128], bHHt  [MAXS * 128];
__device__ float bHnH  [MAXS * 128], bHnT  [MAXS * 128];
__device__ float bZH   [MAXS * 512], bZT   [MAXS * 512];

// ---------------- grid barrier ----------------
__device__ unsigned g_barCnt;            // zero-init
__device__ volatile unsigned g_barGen;   // zero-init

__device__ __forceinline__ void grid_barrier() {
  __syncthreads();
  if (threadIdx.x == 0) {
    unsigned gen = g_barGen;
    __threadfence();
    if (atomicAdd(&g_barCnt, 1u) == gridDim.x - 1) {
      g_barCnt = 0;
      __threadfence();
      g_barGen = gen + 1;
    } else {
      while (g_barGen == gen) { __nanosleep(32); }
    }
    __threadfence();
  }
  __syncthreads();
}

__device__ __forceinline__ float sigf(float x) { return 1.0f / (1.0f + expf(-x)); }

__device__ __forceinline__ void FFMA2(ull &d, ull a, ull b) {
  asm("fma.rn.f32x2 %0, %1, %2, %0;" : "+l"(d) : "l"(a), "l"(b));
}

// ============================================================================
// Scheduler: hash compaction + peeling into waves. One block, 1024 threads.
// ============================================================================
__global__ void __launch_bounds__(1024) scheduler_kernel(const int* heads, const int* tails, int S) {
  __shared__ int buf[HSIZE];
  __shared__ unsigned short sCH[MAXS], sCT[MAXS];
  __shared__ unsigned char asg[MAXS];
  __shared__ int sCnt, sBase, sW, sRemain;

  const int tid = threadIdx.x;

  for (int i = tid; i < HSIZE; i += 1024) { buf[i] = 0; g_slotNode[i] = -1; }
  for (int s = tid; s < S; s += 1024) asg[s] = 0;
  for (int i = tid; i < 4096; i += 1024) g_tick[i] = 0;
  if (tid == 0) { sBase = 0; sW = 0; sRemain = S; }
  __syncthreads();

  // ---- insertion: slot = compact id ----
  for (int i = tid; i < 2 * S; i += 1024) {
    int step = i >> 1, isT = i & 1;
    int node = isT ? tails[step] : heads[step];
    int key = node + 1;
    unsigned slot = ((unsigned)node * 2654435761u) & HMASK;
    while (true) {
      int cur = buf[slot];
      if (cur == key) break;
      if (cur == 0) {
        int old = atomicCAS(&buf[slot], 0, key);
        if (old == 0) { g_slotNode[slot] = node; break; }
        if (old == key) break;
      }
      slot = (slot + 1u) & HMASK;
    }
    if (isT) { sCT[step] = (unsigned short)slot; g_cidT[step] = (int)slot; }
    else     { sCH[step] = (unsigned short)slot; g_cidH[step] = (int)slot; }
  }
  __syncthreads();

  // ---- peeling into waves ----
  while (sRemain > 0) {
    for (int s = tid; s < S; s += 1024)
      if (!asg[s]) { buf[sCH[s]] = 0x7FFFFFFF; buf[sCT[s]] = 0x7FFFFFFF; }
    __syncthreads();
    for (int s = tid; s < S; s += 1024)
      if (!asg[s]) {
        atomicMin(&buf[sCH[s]], 2 * s);
        atomicMin(&buf[sCT[s]], 2 * s + 1);
      }
    if (tid == 0) sCnt = 0;
    __syncthreads();
    for (int s = tid; s < S; s += 1024)
      if (!asg[s]) {
        int ch = sCH[s], ct = sCT[s];
        if (buf[ch] == 2 * s && (ct == ch || buf[ct] == 2 * s + 1)) {
          asg[s] = 1;
          int pos = atomicAdd(&sCnt, 1);
          g_stepList[sBase + pos] = s;
        }
      }
    __syncthreads();
    if (tid == 0) {
      g_waveOff[sW] = sBase;
      sBase += sCnt;
      sRemain -= sCnt;
      sW += 1;
      g_waveOff[sW] = sBase;
    }
    __syncthreads();
  }
  if (tid == 0) g_numWaves = sW;
}

// ============================================================================
// 16x128 GEMM tile, f32x2 packed FFMA, 2x4 micro-tile per thread (256 thr).
// Y[tile] = epi( A1@W1 (+ A2@W2) + bias ), K=128 per operand pair.
// A rows / outputs via per-row pointers (fused gather/scatter; null => skip).
// ============================================================================
__device__ void gemm16(const float* __restrict__ W1, const float* __restrict__ W2,
                       bool dual, int ldw, int n0,
                       const float* __restrict__ bias, int epi,
                       const float* const* sA1, const float* const* sA2,
                       float* const* sOut, const float* sDec,
                       float (*AsT2)[32], float (*Ws)[128]) {
  const int tid = threadIdx.x;
  const int wid = tid >> 5;
  const int lane = tid & 31;

  ull acc00 = 0, acc01 = 0, acc10 = 0, acc11 = 0;

  const int npair = dual ? 2 : 1;
  for (int pair = 0; pair < npair; ++pair) {
    for (int k0 = 0; k0 < 128; k0 += 32) {
      if (tid < 128) {
        int r = tid & 15;
        int kq = (tid >> 4) << 2;
        const float* src = pair ? sA2[r] : sA1[r];
        float4 av = *(const float4*)(src + k0 + kq);
        *(float2*)&AsT2[kq + 0][2 * r] = make_float2(av.x, av.x);
        *(float2*)&AsT2[kq + 1][2 * r] = make_float2(av.y, av.y);
        *(float2*)&AsT2[kq + 2][2 * r] = make_float2(av.z, av.z);
        *(float2*)&AsT2[kq + 3][2 * r] = make_float2(av.w, av.w);
      }
#pragma unroll
      for (int j = 0; j < 4; ++j) {
        int lin = tid + j * NTHR;
        int kk = lin >> 5, c4 = (lin & 31) << 2;
        *(float4*)&Ws[kk][c4] = *(const float4*)(W1 == 0 ? 0 :
            ((pair ? W2 : W1) + (size_t)(k0 + kk) * ldw + n0 + c4));
      }
      __syncthreads();
#pragma unroll
      for (int kk = 0; kk < 32; ++kk) {
        ull a0 = *(const ull*)&AsT2[kk][4 * wid];
        ull a1 = *(const ull*)&AsT2[kk][4 * wid + 2];
        ulonglong2 wv = *(const ulonglong2*)&Ws[kk][lane << 2];
        FFMA2(acc00, a0, wv.x); FFMA2(acc01, a0, wv.y);
        FFMA2(acc10, a1, wv.x); FFMA2(acc11, a1, wv.y);
      }
      __syncthreads();
    }
  }

  union U { ull u; float2 f; };
#pragma unroll
  for (int i = 0; i < 2; i++) {
    int r = 2 * wid + i;
    float* o = sOut[r];
    if (!o) continue;
    U u0, u1;
    u0.u = i ? acc10 : acc00;
    u1.u = i ? acc11 : acc01;
    float vals[4] = {u0.f.x, u0.f.y, u1.f.x, u1.f.y};
#pragma unroll
    for (int j = 0; j < 4; j++) {
      int cin = (lane << 2) + j;
      float v = vals[j];
      if (bias) v += bias[cin];
      if (epi == EPI_TANH) {
        v = tanhf(v);
      } else if (epi == EPI_CADJ) {
        float cs = tanhf(v);
        float cp = sA1[r][cin];
        v = cp + cs * (sDec[r] - 1.0f);
      }
      o[cin] = v;
    }
  }
}

// ============================================================================
// Persistent cooperative main kernel (init gather + waves). 2 blocks/SM.
// ============================================================================
__global__ void __launch_bounds__(NTHR, 2) main_kernel(Params p) {
  __shared__ float AsT2[32][32];
  __shared__ float Ws[32][128];
  __shared__ const float* sA1[16];
  __shared__ const float* sA2[16];
  __shared__ float* sOut[16];
  __shared__ float sDec[16];
  __shared__ int sJob;

  const int tid = threadIdx.x;
  const int gsize = gridDim.x * blockDim.x;
  const int gtid = blockIdx.x * blockDim.x + tid;
  const int S = p.S;

  // -------- init gather of touched rows into compact tables ---------------
  for (int e = gtid; e < HSIZE * 32; e += gsize) {
    int slot = e >> 5, q = (e & 31) << 2;
    int node = g_slotNode[slot];
    if (node < 0) continue;
    size_t src = (size_t)node * 128 + q;
    size_t dst = (size_t)slot * 128 + q;
    *(float4*)&c_rep[dst] = *(const float4*)&p.node_rep[src];
    *(float4*)&c_ch[dst]  = *(const float4*)&p.cell_head[src];
    *(float4*)&c_hh[dst]  = *(const float4*)&p.hidden_head[src];
    *(float4*)&c_ct[dst]  = *(const float4*)&p.cell_tail[src];
    *(float4*)&c_ht[dst]  = *(const float4*)&p.hidden_tail[src];
    if (q == 0) c_rt[slot] = 0.0f;
  }
  grid_barrier();

  const int nW = g_numWaves;

  for (int w = 0; w < nW; ++w) {
    const int s0 = g_waveOff[w];
    const int M = g_waveOff[w + 1] - s0;
    const int mT = (M + 15) >> 4;
    int* tick = &g_tick[(w * 3) & 4095];

    // -------- Phase B: edge GEMMs, cadj GEMMs, copies --------
    {
      const int nJobs = mT * 5;
      for (;;) {
        __syncthreads();
        if (tid == 0) sJob = atomicAdd(&tick[0], 1);
        __syncthreads();
        int j = sJob;
        if (j >= nJobs) break;
        if (j >= 4 * mT) {
          // copy job: out emission + pre-update hidden stash
          int m0 = (j - 4 * mT) * 16;
          for (int l = tid; l < 16 * 32; l += NTHR) {
            int r = l >> 5, q = (l & 31) << 2;
            int m = m0 + r;
            if (m >= M) continue;
            int step = g_stepList[s0 + m];
            int ch = g_cidH[step], ct = g_cidT[step];
            float4 rh = *(const float4*)&c_rep[ch * 128 + q];
            float4 rt = *(const float4*)&c_rep[ct * 128 + q];
            *(float4*)&p.out[(size_t)step * 128 + q] = rh;
            *(float4*)&p.out[(size_t)(S + step) * 128 + q] = rt;
            *(float4*)&bHTh[m * 128 + q] = *(const float4*)&c_ht[ch * 128 + q];
            *(float4*)&bHHt[m * 128 + q] = *(const float4*)&c_hh[ct * 128 + q];
          }
          continue;
        }
        int kind, m0;
        if (j < 2 * mT) { kind = j & 1; m0 = (j >> 1) * 16; }            // edge
        else { int jj = j - 2 * mT; kind = 2 + (jj & 1); m0 = (jj >> 1) * 16; }  // cadj
        if (tid < 16) {
          int m = m0 + tid;
          bool v = m < M;
          int step = g_stepList[s0 + (v ? m : 0)];
          int ch = g_cidH[step], ct = g_cidT[step];
          const float *a1, *a2 = 0; float* o = 0; float dc = 1.0f;
          if (kind == 0)      { a1 = c_rep + ch * 128; a2 = c_rep + ct * 128; o = bEdgeH + m * 128; }
          else if (kind == 1) { a1 = c_rep + ch * 128; a2 = c_rep + ct * 128; o = bEdgeT + m * 128; }
          else if (kind == 2) { a1 = c_ch + ch * 128; o = bCadjH + m * 128;
                                dc = expf(-(p.times[step] - c_rt[ch])); }
          else                { a1 = c_ct + ct * 128; o = bCadjT + m * 128;
                                dc = expf(-(p.times[step] - c_rt[ct])); }
          sA1[tid] = a1; sA2[tid] = a2; sOut[tid] = v ? o : 0; sDec[tid] = dc;
        }
        __syncthreads();
        if (kind == 0)
          gemm16(p.Weh1, p.Weh2, true, 128, 0, p.beh, EPI_TANH, sA1, sA2, sOut, sDec, AsT2, Ws);
        else if (kind == 1)
          gemm16(p.Wet1, p.Wet2, true, 128, 0, p.bet, EPI_TANH, sA1, sA2, sOut, sDec, AsT2, Ws);
        else if (kind == 2)
          gemm16(p.Wdh, 0, false, 128, 0, p.bdh, EPI_CADJ, sA1, sA2, sOut, sDec, AsT2, Ws);
        else
          gemm16(p.Wdt, 0, false, 128, 0, p.bdt, EPI_CADJ, sA1, sA2, sOut, sDec, AsT2, Ws);
      }
    }
    grid_barrier();

    // -------- Phase C: LSTM gate GEMMs (z = edge@Wx + h@Wh + b), N=512 -----
    {
      const int nJobs = mT * 8;
      for (;;) {
        __syncthreads();
        if (tid == 0) sJob = atomicAdd(&tick[1], 1);
        __syncthreads();
        int j = sJob;
        if (j >= nJobs) break;
        int side = j & 1, nt = (j >> 1) & 3, mt = j >> 3;
        int m0 = mt * 16, n0 = nt * 128;
        if (tid < 16) {
          int m = m0 + tid;
          bool v = m < M;
          int step = g_stepList[s0 + (v ? m : 0)];
          if (side == 0) {
            int ch = g_cidH[step];
            sA1[tid] = bEdgeH + m * 128;
            sA2[tid] = c_hh + ch * 128;
            sOut[tid] = v ? (bZH + m * 512 + n0) : 0;
          } else {
            int ct = g_cidT[step];
            sA1[tid] = bEdgeT + m * 128;
            sA2[tid] = c_ht + ct * 128;
            sOut[tid] = v ? (bZT + m * 512 + n0) : 0;
          }
        }
        __syncthreads();
        if (side == 0)
          gemm16(p.Wxh, p.Whh, true, 512, n0, p.bh + n0, EPI_NONE, sA1, sA2, sOut, sDec, AsT2, Ws);
        else
          gemm16(p.Wxt, p.Wht, true, 512, n0, p.bt + n0, EPI_NONE, sA1, sA2, sOut, sDec, AsT2, Ws);
      }
    }
    grid_barrier();

    // -------- Phase D: gates elementwise + cell/hidden/rt scatter ---------
    for (int e = gtid; e < M * 128; e += gsize) {
      int s = e >> 7, d = e & 127;
      int step = g_stepList[s0 + s];
      int ch = g_cidH[step], ct = g_cidT[step];
      {
        float zi = bZH[s * 512 + d];
        float zf = bZH[s * 512 + 128 + d];
        float zo = bZH[s * 512 + 256 + d];
        float zg = bZH[s * 512 + 384 + d];
        float ii = sigf(zi), ff = sigf(zf), oo = sigf(zo), gg = tanhf(zg);
        float cn = ff * bCadjH[s * 128 + d] + ii * gg;
        float hn = oo * tanhf(cn);
        bHnH[s * 128 + d] = hn;
        c_ch[ch * 128 + d] = cn;
        c_hh[ch * 128 + d] = hn;
      }
      {
        float zi = bZT[s * 512 + d];
        float zf = bZT[s * 512 + 128 + d];
        float zo = bZT[s * 512 + 256 + d];
        float zg = bZT[s * 512 + 384 + d];
        float ii = sigf(zi), ff = sigf(zf), oo = sigf(zo), gg = tanhf(zg);
        float cn = ff * bCadjT[s * 128 + d] + ii * gg;
        float hn = oo * tanhf(cn);
        bHnT[s * 128 + d] = hn;
        c_ct[ct * 128 + d] = cn;
        c_ht[ct * 128 + d] = hn;
      }
      if (d == 0) {
        float tm = p.times[step];
        c_rt[ch] = tm;
        c_rt[ct] = tm;
      }
    }
    grid_barrier();

    // -------- Phase E: combiner GEMMs with fused rep scatter ---------------
    {
      const int nJobs = mT * 2;
      for (;;) {
        __syncthreads();
        if (tid == 0) sJob = atomicAdd(&tick[2], 1);
        __syncthreads();
        int j = sJob;
        if (j >= nJobs) break;
        int side = j & 1, mt = j >> 1;
        int m0 = mt * 16;
        if (tid < 16) {
          int m = m0 + tid;
          bool v = m < M;
          int step = g_stepList[s0 + (v ? m : 0)];
          int ch = g_cidH[step], ct = g_cidT[step];
          if (side == 0) {
            sA1[tid] = bHnH + m * 128;
            sA2[tid] = bHTh + m * 128;
            sOut[tid] = (v && ch != ct) ? (c_rep + ch * 128) : 0;  // tail wins on h==t
          } else {
            sA1[tid] = bHHt + m * 128;
            sA2[tid] = bHnT + m * 128;
            sOut[tid] = v ? (c_rep + ct * 128) : 0;
          }
        }
        __syncthreads();
        gemm16(p.Wc1, p.Wc2, true, 128, 0, 0, EPI_TANH, sA1, sA2, sOut, sDec, AsT2, Ws);
      }
    }
    grid_barrier();
  }
}

// ============================================================================
extern "C" void kernel_launch(void* const* d_in, const int* in_sizes, int n_in,
                              void* d_out, int out_size) {
  Params p;
  p.heads       = (const int*)d_in[0];
  p.tails       = (const int*)d_in[1];
  p.times       = (const float*)d_in[2];
  p.node_rep    = (const float*)d_in[3];
  p.cell_head   = (const float*)d_in[4];
  p.hidden_head = (const float*)d_in[5];
  p.cell_tail   = (const float*)d_in[6];
  p.hidden_tail = (const float*)d_in[7];
  p.Weh1 = (const float*)d_in[8];
  p.Weh2 = (const float*)d_in[9];
  p.beh  = (const float*)d_in[10];
  p.Wet1 = (const float*)d_in[11];
  p.Wet2 = (const float*)d_in[12];
  p.bet  = (const float*)d_in[13];
  p.Wxh  = (const float*)d_in[14];
  p.Whh  = (const float*)d_in[15];
  p.bh   = (const float*)d_in[16];
  p.Wdh  = (const float*)d_in[17];
  p.bdh  = (const float*)d_in[18];
  p.Wxt  = (const float*)d_in[19];
  p.Wht  = (const float*)d_in[20];
  p.bt   = (const float*)d_in[21];
  p.Wdt  = (const float*)d_in[22];
  p.bdt  = (const float*)d_in[23];
  p.Wc1  = (const float*)d_in[24];
  p.Wc2  = (const float*)d_in[25];
  p.out  = (float*)d_out;
  p.S    = in_sizes[0];

  scheduler_kernel<<<1, 1024>>>(p.heads, p.tails, p.S);
  main_kernel<<<NBLK, NTHR>>>(p);
}

// round 9
// speedup vs baseline: 2.0276x; 1.2683x over previous
#include <cuda_runtime.h>
#include <math.h>
#include <stdint.h>

#define MAXS 2048
#define HSIZE 8192
#define HMASK 8191
#define NBLK 296
#define NTHR 256
#define SMEMF 28800            // dynamic smem floats per block (112.5KB)
#define TILE_MIN 224

#define EPI_NONE 0
#define EPI_TANH 1
#define EPI_CADJ 2

typedef unsigned long long ull;

struct Params {
  const int *heads, *tails;
  const float *times;
  const float *node_rep, *cell_head, *hidden_head, *cell_tail, *hidden_tail;
  const float *Weh1, *Weh2, *beh, *Wet1, *Wet2, *bet;
  const float *Wxh, *Whh, *bh, *Wdh, *bdh;
  const float *Wxt, *Wht, *bt, *Wdt, *bdt;
  const float *Wc1, *Wc2;
  float *out;
  int S;
};

__device__ int g_cidH[MAXS], g_cidT[MAXS];
__device__ int g_slotNode[HSIZE];
__device__ int g_stepList[MAXS];
__device__ int g_waveOff[MAXS + 2];
__device__ int g_numWaves;

__device__ float c_rep[HSIZE * 128];
__device__ float c_ch [HSIZE * 128];
__device__ float c_hh [HSIZE * 128];
__device__ float c_ct [HSIZE * 128];
__device__ float c_ht [HSIZE * 128];
__device__ float c_rt [HSIZE];

__device__ unsigned g_barCnt;
__device__ volatile unsigned g_barGen;

__device__ __forceinline__ void grid_barrier() {
  __syncthreads();
  if (threadIdx.x == 0) {
    unsigned gen = g_barGen;
    __threadfence();
    if (atomicAdd(&g_barCnt, 1u) == gridDim.x - 1) {
      g_barCnt = 0; __threadfence(); g_barGen = gen + 1;
    } else {
      while (g_barGen == gen) { __nanosleep(32); }
    }
    __threadfence();
  }
  __syncthreads();
}

__device__ __forceinline__ float sigf(float x) { return 1.0f / (1.0f + expf(-x)); }
__device__ __forceinline__ void FFMA2(ull &d, ull a, ull b) {
  asm("fma.rn.f32x2 %0, %1, %2, %0;" : "+l"(d) : "l"(a), "l"(b));
}
__device__ __forceinline__ ull pack2(float a) {
  ull d; asm("mov.b64 %0, {%1, %1};" : "=l"(d) : "f"(a)); return d;
}
__device__ __forceinline__ void cpa16(uint32_t s, const float* g) {
  asm volatile("cp.async.cg.shared.global [%0], [%1], 16;" :: "r"(s), "l"(g));
}
#define CPA_COMMIT() asm volatile("cp.async.commit_group;")
#define CPA_WAIT1()  asm volatile("cp.async.wait_group 1;")
#define CPA_WAIT0()  asm volatile("cp.async.wait_group 0;")

// ============================ scheduler =====================================
__global__ void __launch_bounds__(1024) scheduler_kernel(const int* heads, const int* tails, int S) {
  __shared__ int buf[HSIZE];
  __shared__ unsigned short sCH[MAXS], sCT[MAXS];
  __shared__ unsigned char asg[MAXS];
  __shared__ int sCnt, sBase, sW, sRemain;
  const int tid = threadIdx.x;
  for (int i = tid; i < HSIZE; i += 1024) { buf[i] = 0; g_slotNode[i] = -1; }
  for (int s = tid; s < S; s += 1024) asg[s] = 0;
  if (tid == 0) { sBase = 0; sW = 0; sRemain = S; }
  __syncthreads();
  for (int i = tid; i < 2 * S; i += 1024) {
    int step = i >> 1, isT = i & 1;
    int node = isT ? tails[step] : heads[step];
    int key = node + 1;
    unsigned slot = ((unsigned)node * 2654435761u) & HMASK;
    while (true) {
      int cur = buf[slot];
      if (cur == key) break;
      if (cur == 0) {
        int old = atomicCAS(&buf[slot], 0, key);
        if (old == 0) { g_slotNode[slot] = node; break; }
        if (old == key) break;
      }
      slot = (slot + 1u) & HMASK;
    }
    if (isT) { sCT[step] = (unsigned short)slot; g_cidT[step] = (int)slot; }
    else     { sCH[step] = (unsigned short)slot; g_cidH[step] = (int)slot; }
  }
  __syncthreads();
  while (sRemain > 0) {
    for (int s = tid; s < S; s += 1024)
      if (!asg[s]) { buf[sCH[s]] = 0x7FFFFFFF; buf[sCT[s]] = 0x7FFFFFFF; }
    __syncthreads();
    for (int s = tid; s < S; s += 1024)
      if (!asg[s]) { atomicMin(&buf[sCH[s]], 2 * s); atomicMin(&buf[sCT[s]], 2 * s + 1); }
    if (tid == 0) sCnt = 0;
    __syncthreads();
    for (int s = tid; s < S; s += 1024)
      if (!asg[s]) {
        int ch = sCH[s], ct = sCT[s];
        if (buf[ch] == 2 * s && (ct == ch || buf[ct] == 2 * s + 1)) {
          asg[s] = 1;
          g_stepList[sBase + atomicAdd(&sCnt, 1)] = s;
        }
      }
    __syncthreads();
    if (tid == 0) {
      g_waveOff[sW] = sBase; sBase += sCnt; sRemain -= sCnt; sW += 1; g_waveOff[sW] = sBase;
    }
    __syncthreads();
  }
  if (tid == 0) g_numWaves = sW;
}

// ==================== tiled GEMM (16 rows x 128 cols) =======================
// out = epi(A1@W1 (+A2@W2) + bias). A in smem [16*128]. W streamed cp.async.
// zpass>=0: column map col -> (col>>5)*128 + zpass*32 + (col&31) for W/bias.
struct GArgs {
  const float *A1, *A2, *W1, *W2, *bias, *CA, *dec;
  float *outS; float* const* outG; float* sW;
  int ldw, zpass, epi;
};
__device__ void gemmT(const GArgs& a) {
  const int tid = threadIdx.x;
  const int w = tid >> 5, l = tid & 31;
  const int r0 = w << 1;
  const int nch = a.A2 ? 8 : 4;
  // stage chunk 0
  {
    const float* W = a.W1; int k0 = 0;
    float* Wb = a.sW;
#pragma unroll
    for (int i = 0; i < 4; ++i) {
      int e = tid + i * NTHR, kk = e >> 5, c4 = (e & 31) << 2;
      int col = (a.zpass >= 0) ? ((c4 >> 5) * 128 + a.zpass * 32 + (c4 & 31)) : c4;
      cpa16((uint32_t)__cvta_generic_to_shared(Wb + kk * 128 + c4),
            W + (size_t)(k0 + kk) * a.ldw + col);
    }
    CPA_COMMIT();
  }
  ull ac00 = 0, ac01 = 0, ac10 = 0, ac11 = 0;
  for (int c = 0; c < nch; ++c) {
    if (c + 1 < nch) {
      const float* W = (c + 1 >= 4) ? a.W2 : a.W1;
      int k0 = ((c + 1) & 3) * 32;
      float* Wb = a.sW + ((c + 1) & 1) * 4096;
#pragma unroll
      for (int i = 0; i < 4; ++i) {
        int e = tid + i * NTHR, kk = e >> 5, c4 = (e & 31) << 2;
        int col = (a.zpass >= 0) ? ((c4 >> 5) * 128 + a.zpass * 32 + (c4 & 31)) : c4;
        cpa16((uint32_t)__cvta_generic_to_shared(Wb + kk * 128 + c4),
              W + (size_t)(k0 + kk) * a.ldw + col);
      }
      CPA_COMMIT();
      CPA_WAIT1();
    } else {
      CPA_WAIT0();
    }
    __syncthreads();
    const float* A = (c >= 4) ? a.A2 : a.A1;
    const int k0 = (c & 3) * 32;
    const float* Wb = a.sW + (c & 1) * 4096;
#pragma unroll
    for (int kk = 0; kk < 32; ++kk) {
      ull A0 = pack2(A[r0 * 128 + k0 + kk]);
      ull A1v = pack2(A[(r0 + 1) * 128 + k0 + kk]);
      ulonglong2 wv = *(const ulonglong2*)&Wb[kk * 128 + (l << 2)];
      FFMA2(ac00, A0, wv.x); FFMA2(ac01, A0, wv.y);
      FFMA2(ac10, A1v, wv.x); FFMA2(ac11, A1v, wv.y);
    }
    __syncthreads();
  }
  union U { ull u; float2 f; };
#pragma unroll
  for (int i = 0; i < 2; ++i) {
    int r = r0 + i;
    U u0, u1; u0.u = i ? ac10 : ac00; u1.u = i ? ac11 : ac01;
    float vals[4] = {u0.f.x, u0.f.y, u1.f.x, u1.f.y};
    float* og = a.outG ? a.outG[r] : 0;
#pragma unroll
    for (int j = 0; j < 4; ++j) {
      int col = (l << 2) + j;
      float v = vals[j];
      if (a.bias) {
        int bc = (a.zpass >= 0) ? ((col >> 5) * 128 + a.zpass * 32 + (col & 31)) : col;
        v += a.bias[bc];
      }
      if (a.epi == EPI_TANH) v = tanhf(v);
      else if (a.epi == EPI_CADJ) {
        float cs = tanhf(v);
        v = a.CA[r * 128 + col] + cs * (a.dec[r] - 1.0f);
      }
      if (a.outS) a.outS[r * 128 + col] = v;
      else if (og) og[col] = v;
    }
  }
  __syncthreads();
}

// ============================== main kernel =================================
__global__ void __launch_bounds__(NTHR, 2) main_kernel(Params p) {
  extern __shared__ float sm[];
  float *X1 = sm, *X2 = sm + 2048, *E1 = sm + 4096, *E2 = sm + 6144;
  float *H1 = sm + 8192, *H2 = sm + 10240, *S1 = sm + 12288, *S2 = sm + 14336;
  float *Z = sm + 16384, *CA = sm + 18432, *WS = sm + 20480;
  int   *slotH = (int*)(sm + 28672), *slotT = slotH + 16, *valid = slotT + 16;
  float *decH = (float*)(valid + 16), *decT = decH + 16;
  float **og = (float**)(decT + 16);   // 16 ptrs

  const int tid = threadIdx.x;
  const int gsize = gridDim.x * blockDim.x;
  const int gtid = blockIdx.x * blockDim.x + tid;
  const int S = p.S;

  // init gather
  for (int e = gtid; e < HSIZE * 32; e += gsize) {
    int slot = e >> 5, q = (e & 31) << 2;
    int node = g_slotNode[slot];
    if (node < 0) continue;
    size_t src = (size_t)node * 128 + q;
    size_t dst = (size_t)slot * 128 + q;
    *(float4*)&c_rep[dst] = *(const float4*)&p.node_rep[src];
    *(float4*)&c_ch[dst]  = *(const float4*)&p.cell_head[src];
    *(float4*)&c_hh[dst]  = *(const float4*)&p.hidden_head[src];
    *(float4*)&c_ct[dst]  = *(const float4*)&p.cell_tail[src];
    *(float4*)&c_ht[dst]  = *(const float4*)&p.hidden_tail[src];
    if (q == 0) c_rt[slot] = 0.0f;
  }
  grid_barrier();

  const int nW = g_numWaves;
  for (int w = 0; w < nW; ++w) {
    const int s0 = g_waveOff[w];
    const int M = g_waveOff[w + 1] - s0;

    if (M >= TILE_MIN) {
      // ================= tiled path: 16 steps per block-job =================
      const int mT = (M + 15) >> 4;
      for (int job = blockIdx.x; job < mT; job += gridDim.x) {
        int m0 = job * 16;
        if (tid < 16) {
          int m = m0 + tid;
          int v = (m < M);
          int step = g_stepList[s0 + (v ? m : (M - 1))];
          int ch = g_cidH[step], ct = g_cidT[step];
          slotH[tid] = ch; slotT[tid] = ct; valid[tid] = v;
          float tm = p.times[step];
          decH[tid] = expf(-(tm - c_rt[ch]));
          decT[tid] = expf(-(tm - c_rt[ct]));
          if (v) { c_rt[ch] = tm; c_rt[ct] = tm; }
        }
        __syncthreads();
        // gather + output emit
        for (int e = tid; e < 512; e += NTHR) {
          int r = e >> 5, q = (e & 31) << 2;
          int ch = slotH[r], ct = slotT[r];
          float4 rh = *(const float4*)&c_rep[ch * 128 + q];
          float4 rt = *(const float4*)&c_rep[ct * 128 + q];
          *(float4*)&X1[r * 128 + q] = rh;
          *(float4*)&X2[r * 128 + q] = rt;
          *(float4*)&H1[r * 128 + q] = *(const float4*)&c_hh[ch * 128 + q];
          *(float4*)&H2[r * 128 + q] = *(const float4*)&c_ht[ct * 128 + q];
          *(float4*)&S1[r * 128 + q] = *(const float4*)&c_ht[ch * 128 + q];
          *(float4*)&S2[r * 128 + q] = *(const float4*)&c_hh[ct * 128 + q];
          if (valid[r]) {
            int step = g_stepList[s0 + m0 + r];
            *(float4*)&p.out[(size_t)step * 128 + q] = rh;
            *(float4*)&p.out[(size_t)(S + step) * 128 + q] = rt;
          }
        }
        __syncthreads();
        GArgs a; a.sW = WS; a.CA = 0; a.dec = 0; a.outG = 0; a.zpass = -1;
        // edges
        a.A1 = X1; a.A2 = X2; a.W1 = p.Weh1; a.W2 = p.Weh2; a.ldw = 128;
        a.bias = p.beh; a.epi = EPI_TANH; a.outS = E1; gemmT(a);
        a.W1 = p.Wet1; a.W2 = p.Wet2; a.bias = p.bet; a.outS = E2; gemmT(a);
        // cadj head
        for (int e = tid; e < 512; e += NTHR) {
          int r = e >> 5, q = (e & 31) << 2;
          *(float4*)&CA[r * 128 + q] = *(const float4*)&c_ch[slotH[r] * 128 + q];
        }
        __syncthreads();
        a.A1 = CA; a.A2 = 0; a.W1 = p.Wdh; a.W2 = 0; a.bias = p.bdh;
        a.epi = EPI_CADJ; a.CA = CA; a.dec = decH; a.outS = X1; gemmT(a);
        // cadj tail
        for (int e = tid; e < 512; e += NTHR) {
          int r = e >> 5, q = (e & 31) << 2;
          *(float4*)&CA[r * 128 + q] = *(const float4*)&c_ct[slotT[r] * 128 + q];
        }
        __syncthreads();
        a.W1 = p.Wdt; a.bias = p.bdt; a.dec = decT; a.outS = X2; gemmT(a);
        // gates per side, 4 col passes
        for (int side = 0; side < 2; ++side) {
          float* E = side ? E2 : E1;
          float* Hs = side ? H2 : H1;
          float* Xc = side ? X2 : X1;
          float* cel = side ? c_ct : c_ch;
          float* hid = side ? c_ht : c_hh;
          int* slot = side ? slotT : slotH;
          GArgs b; b.sW = WS; b.A1 = E; b.A2 = Hs;
          b.W1 = side ? p.Wxt : p.Wxh; b.W2 = side ? p.Wht : p.Whh;
          b.ldw = 512; b.bias = side ? p.bt : p.bh; b.epi = EPI_NONE;
          b.CA = 0; b.dec = 0; b.outS = Z; b.outG = 0;
          for (int pass = 0; pass < 4; ++pass) {
            b.zpass = pass; gemmT(b);
            for (int e = tid; e < 512; e += NTHR) {
              int r = e >> 5, c = e & 31;
              if (!valid[r]) continue;
              float ii = sigf(Z[r * 128 + c]);
              float ff = sigf(Z[r * 128 + 32 + c]);
              float oo = sigf(Z[r * 128 + 64 + c]);
              float gg = tanhf(Z[r * 128 + 96 + c]);
              int col = pass * 32 + c;
              float cn = ff * Xc[r * 128 + col] + ii * gg;
              float hn = oo * tanhf(cn);
              Xc[r * 128 + col] = hn;
              cel[slot[r] * 128 + col] = cn;
              hid[slot[r] * 128 + col] = hn;
            }
            __syncthreads();
          }
        }
        // combiner head: tanh(hnH@Wc1 + S1@Wc2) -> c_rep[ch] (skip if ch==ct)
        if (tid < 16)
          og[tid] = (valid[tid] && slotH[tid] != slotT[tid]) ? (c_rep + slotH[tid] * 128) : 0;
        __syncthreads();
        a.A1 = X1; a.A2 = S1; a.W1 = p.Wc1; a.W2 = p.Wc2; a.ldw = 128;
        a.bias = 0; a.epi = EPI_TANH; a.CA = 0; a.dec = 0;
        a.outS = 0; a.outG = og; gemmT(a);
        if (tid < 16) og[tid] = valid[tid] ? (c_rep + slotT[tid] * 128) : 0;
        __syncthreads();
        a.A1 = S2; a.A2 = X2; gemmT(a);
      }
    } else {
      // ================= GEMV path: one step per block-job ==================
      float *aRH = sm, *aRT = sm + 128, *aHH = sm + 256, *aHT = sm + 384;
      float *aTh = sm + 512, *aHt = sm + 640, *aCH = sm + 768, *aCT = sm + 896;
      float *eH = sm + 1024, *eT = sm + 1152, *cjH = sm + 1280, *cjT = sm + 1408;
      float *hnH = sm + 1536, *hnT = sm + 1664;
      float *zz = sm + 1792;             // [2][512]
      float *dc = sm + 2816;             // dc[0]=decH, dc[1]=decT
      for (int job = blockIdx.x; job < M; job += gridDim.x) {
        int step = g_stepList[s0 + job];
        int ch = g_cidH[step], ct = g_cidT[step];
        if (tid == 0) {
          float tm = p.times[step];
          dc[0] = expf(-(tm - c_rt[ch]));
          dc[1] = expf(-(tm - c_rt[ct]));
          c_rt[ch] = tm; c_rt[ct] = tm;
        }
        for (int e = tid; e < 128; e += NTHR) { } // (tid<128 covers all below)
        if (tid < 128) {
          int t = tid;
          float rh = c_rep[ch * 128 + t], rt = c_rep[ct * 128 + t];
          aRH[t] = rh; aRT[t] = rt;
          aHH[t] = c_hh[ch * 128 + t]; aHT[t] = c_ht[ct * 128 + t];
          aTh[t] = c_ht[ch * 128 + t]; aHt[t] = c_hh[ct * 128 + t];
          aCH[t] = c_ch[ch * 128 + t]; aCT[t] = c_ct[ct * 128 + t];
          p.out[(size_t)step * 128 + t] = rh;
          p.out[(size_t)(S + step) * 128 + t] = rt;
        }
        __syncthreads();
        if (tid < 64) {          // edge GEMVs: 2 sides x 32 quads
          int side = tid >> 5, q = (tid & 31) << 2;
          const float *W1 = side ? p.Wet1 : p.Weh1, *W2 = side ? p.Wet2 : p.Weh2;
          const float *bb = side ? p.bet : p.beh;
          float4 acc = *(const float4*)&bb[q];
          for (int k = 0; k < 128; ++k) {
            float a0 = aRH[k], a1 = aRT[k];
            float4 w1 = *(const float4*)&W1[k * 128 + q];
            float4 w2 = *(const float4*)&W2[k * 128 + q];
            acc.x += a0 * w1.x + a1 * w2.x; acc.y += a0 * w1.y + a1 * w2.y;
            acc.z += a0 * w1.z + a1 * w2.z; acc.w += a0 * w1.w + a1 * w2.w;
          }
          float* e = side ? eT : eH;
          e[q] = tanhf(acc.x); e[q + 1] = tanhf(acc.y);
          e[q + 2] = tanhf(acc.z); e[q + 3] = tanhf(acc.w);
        } else if (tid < 128) {  // cadj GEMVs
          int side = (tid >> 5) & 1, q = (tid & 31) << 2;
          const float* Wd = side ? p.Wdt : p.Wdh;
          const float* bd = side ? p.bdt : p.bdh;
          const float* cc = side ? aCT : aCH;
          float d = dc[side];
          float4 acc = *(const float4*)&bd[q];
          for (int k = 0; k < 128; ++k) {
            float a0 = cc[k];
            float4 w = *(const float4*)&Wd[k * 128 + q];
            acc.x += a0 * w.x; acc.y += a0 * w.y; acc.z += a0 * w.z; acc.w += a0 * w.w;
          }
          float* cj = side ? cjT : cjH;
          cj[q] = cc[q] + tanhf(acc.x) * (d - 1.f);
          cj[q + 1] = cc[q + 1] + tanhf(acc.y) * (d - 1.f);
          cj[q + 2] = cc[q + 2] + tanhf(acc.z) * (d - 1.f);
          cj[q + 3] = cc[q + 3] + tanhf(acc.w) * (d - 1.f);
        }
        __syncthreads();
        {                        // gates: 2 sides x 4 gates x 32 quads
          int side = tid >> 7, gate = (tid >> 5) & 3, q = (tid & 31) << 2;
          int col = gate * 128 + q;
          const float* Wx = side ? p.Wxt : p.Wxh;
          const float* Wh = side ? p.Wht : p.Whh;
          const float* bb = side ? p.bt : p.bh;
          const float* e = side ? eT : eH;
          const float* hh = side ? aHT : aHH;
          float4 acc = *(const float4*)&bb[col];
          for (int k = 0; k < 128; ++k) {
            float x = e[k], h = hh[k];
            float4 w1 = *(const float4*)&Wx[k * 512 + col];
            float4 w2 = *(const float4*)&Wh[k * 512 + col];
            acc.x += x * w1.x + h * w2.x; acc.y += x * w1.y + h * w2.y;
            acc.z += x * w1.z + h * w2.z; acc.w += x * w1.w + h * w2.w;
          }
          *(float4*)&zz[side * 512 + col] = acc;
        }
        __syncthreads();
        {                        // elementwise + cell/hidden scatter
          int side = tid >> 7, c = tid & 127;
          const float* z = zz + side * 512;
          float ii = sigf(z[c]), ff = sigf(z[128 + c]), oo = sigf(z[256 + c]), gg = tanhf(z[384 + c]);
          float cn = ff * (side ? cjT[c] : cjH[c]) + ii * gg;
          float hn = oo * tanhf(cn);
          if (side) { hnT[c] = hn; c_ct[ct * 128 + c] = cn; c_ht[ct * 128 + c] = hn; }
          else      { hnH[c] = hn; c_ch[ch * 128 + c] = cn; c_hh[ch * 128 + c] = hn; }
        }
        __syncthreads();
        if (tid < 64) {          // combiner: 2 sides x 32 quads
          int side = tid >> 5, q = (tid & 31) << 2;
          const float* a1 = side ? aHt : hnH;
          const float* a2 = side ? hnT : aTh;
          float4 acc = make_float4(0.f, 0.f, 0.f, 0.f);
          for (int k = 0; k < 128; ++k) {
            float x = a1[k], y = a2[k];
            float4 w1 = *(const float4*)&p.Wc1[k * 128 + q];
            float4 w2 = *(const float4*)&p.Wc2[k * 128 + q];
            acc.x += x * w1.x + y * w2.x; acc.y += x * w1.y + y * w2.y;
            acc.z += x * w1.z + y * w2.z; acc.w += x * w1.w + y * w2.w;
          }
          if (side || ch != ct) {
            float* o = c_rep + (side ? ct : ch) * 128;
            o[q] = tanhf(acc.x); o[q + 1] = tanhf(acc.y);
            o[q + 2] = tanhf(acc.z); o[q + 3] = tanhf(acc.w);
          }
        }
        __syncthreads();
      }
    }
    grid_barrier();
  }
}

// ============================================================================
extern "C" void kernel_launch(void* const* d_in, const int* in_sizes, int n_in,
                              void* d_out, int out_size) {
  Params p;
  p.heads = (const int*)d_in[0];  p.tails = (const int*)d_in[1];
  p.times = (const float*)d_in[2];
  p.node_rep = (const float*)d_in[3];  p.cell_head = (const float*)d_in[4];
  p.hidden_head = (const float*)d_in[5]; p.cell_tail = (const float*)d_in[6];
  p.hidden_tail = (const float*)d_in[7];
  p.Weh1 = (const float*)d_in[8];  p.Weh2 = (const float*)d_in[9];  p.beh = (const float*)d_in[10];
  p.Wet1 = (const float*)d_in[11]; p.Wet2 = (const float*)d_in[12]; p.bet = (const float*)d_in[13];
  p.Wxh = (const float*)d_in[14];  p.Whh = (const float*)d_in[15];  p.bh = (const float*)d_in[16];
  p.Wdh = (const float*)d_in[17];  p.bdh = (const float*)d_in[18];
  p.Wxt = (const float*)d_in[19];  p.Wht = (const float*)d_in[20];  p.bt = (const float*)d_in[21];
  p.Wdt = (const float*)d_in[22];  p.bdt = (const float*)d_in[23];
  p.Wc1 = (const float*)d_in[24];  p.Wc2 = (const float*)d_in[25];
  p.out = (float*)d_out;
  p.S = in_sizes[0];

  static int configured = 0;
  if (!configured) {
    cudaFuncSetAttribute(main_kernel, cudaFuncAttributeMaxDynamicSharedMemorySize, SMEMF * 4);
    configured = 1;
  }
  scheduler_kernel<<<1, 1024>>>(p.heads, p.tails, p.S);
  main_kernel<<<NBLK, NTHR, SMEMF * 4>>>(p);
}